// round 7
// baseline (speedup 1.0000x reference)
#include <cuda_runtime.h>
#include <cuda_fp16.h>

// Problem constants (fixed by the dataset)
constexpr int NN   = 50000;
constexpr int EE   = 1600000;
constexpr int ET   = EE + NN;     // edges + self loops
constexpr int DIN  = 32;
constexpr int HID  = 64;
constexpr int HEADS= 4;
constexpr int F2   = HEADS * HID; // 256
constexpr int DOUT = 32;

// ---------------- scratch (device globals; no allocation allowed) -----------
__device__ __half   g_hx [NN * HID];   // x @ W_gcn  (half gather table)
__device__ float    g_h1 [NN * HID];   // relu(gcn)
__device__ float    g_hg [NN * F2];    // h1 @ W_gat (fp32, for attdot)
__device__ __half   g_hgh[NN * F2];    // h1 @ W_gat (half gather table)
__device__ float    g_out2[NN * F2];   // relu(gat)
__device__ float    g_as [NN * HEADS];
__device__ float    g_ad [NN * HEADS];
__device__ unsigned g_maxenc[2 * HEADS]; // [0..3]=max a_s, [4..7]=max a_d (ordered enc)
__device__ float    g_dinv[NN];
__device__ int      g_deg [NN];
__device__ int      g_rowptr[NN + 1];
__device__ int      g_pos [EE];        // position of edge within its dst row
__device__ int      g_csr [ET];

// order-preserving float <-> uint encoding for atomicMax
__device__ __forceinline__ unsigned fenc(float f) {
    unsigned b = __float_as_uint(f);
    return (b & 0x80000000u) ? ~b : (b | 0x80000000u);
}
__device__ __forceinline__ float fdec(unsigned u) {
    return (u & 0x80000000u) ? __uint_as_float(u & 0x7fffffffu)
                             : __uint_as_float(~u);
}

// ---------------- CSR build -------------------------------------------------
__global__ void init_kernel() {
    int i = blockIdx.x * blockDim.x + threadIdx.x;
    if (i < NN) g_deg[i] = 0;
    if (i < 2 * HEADS) g_maxenc[i] = 0u;   // minimum key
}

__global__ void deg_kernel(const int* __restrict__ ei) {
    int i = blockIdx.x * blockDim.x + threadIdx.x;
    if (i >= EE) return;
    int d = ei[EE + i];
    d = min(max(d, 0), NN - 1);
    g_pos[i] = atomicAdd(&g_deg[d], 1);    // position within row; no 2nd atomic later
}

// single-block exclusive scan over (deg+1) -> rowptr; also dinv
__global__ void scan_kernel() {
    __shared__ int sh[1024];
    const int C = 49;                       // 1024*49 >= NN
    int t = threadIdx.x;
    int start = t * C;
    int end   = min(start + C, NN);
    int sum = 0;
    for (int i = start; i < end; ++i) sum += g_deg[i] + 1;
    sh[t] = sum;
    __syncthreads();
    for (int off = 1; off < 1024; off <<= 1) {
        int v = (t >= off) ? sh[t - off] : 0;
        __syncthreads();
        sh[t] += v;
        __syncthreads();
    }
    int run = sh[t] - sum;                  // exclusive prefix
    for (int i = start; i < end; ++i) {
        g_rowptr[i] = run;
        int d = g_deg[i] + 1;
        g_dinv[i] = rsqrtf((float)d);
        run += d;
    }
    if (t == 1023) g_rowptr[NN] = sh[1023];
}

// plain scatter: edge -> rowptr[dst]+pos ; self-loop at rowptr[dst+1]-1
__global__ void csr_fill_kernel(const int* __restrict__ ei) {
    int i = blockIdx.x * blockDim.x + threadIdx.x;
    if (i >= ET) return;
    if (i < EE) {
        int src = min(max(ei[i], 0), NN - 1);
        int dst = min(max(ei[EE + i], 0), NN - 1);
        g_csr[g_rowptr[dst] + g_pos[i]] = src;
    } else {
        int node = i - EE;
        g_csr[g_rowptr[node + 1] - 1] = node;
    }
}

// ---------------- GEMM 1: hx = x @ W_gcn  (50000x32 @ 32x64), half out ------
__global__ void gemm1_kernel(const float* __restrict__ x,
                             const float* __restrict__ W) {
    __shared__ float Wsh[DIN * HID];        // 8 KB
    for (int i = threadIdx.x; i < DIN * HID; i += blockDim.x) Wsh[i] = W[i];
    __syncthreads();
    int gt   = blockIdx.x * blockDim.x + threadIdx.x;
    int warp = gt >> 5;
    int lane = gt & 31;
    if (warp >= NN) return;
    float xv = x[warp * DIN + lane];
    float a0 = 0.f, a1 = 0.f;
#pragma unroll
    for (int k = 0; k < 32; ++k) {
        float xk = __shfl_sync(0xffffffffu, xv, k);
        a0 += xk * Wsh[k * HID + lane];
        a1 += xk * Wsh[k * HID + 32 + lane];
    }
    g_hx[warp * HID + lane]      = __float2half(a0);
    g_hx[warp * HID + 32 + lane] = __float2half(a1);
}

// ---------------- GCN aggregation: warp per dst, half gathers, unroll 4 -----
__global__ void gcn_agg_kernel(const float* __restrict__ b_gcn) {
    int gt   = blockIdx.x * blockDim.x + threadIdx.x;
    int warp = gt >> 5;
    if (warp >= NN) return;
    int lane = gt & 31;
    int beg = g_rowptr[warp], end = g_rowptr[warp + 1];
    float dd = g_dinv[warp];
    float ax = 0.f, ay = 0.f;
    const __half2* hx2 = (const __half2*)g_hx;
    int j = beg;
    for (; j + 4 <= end; j += 4) {
        int s0 = g_csr[j], s1 = g_csr[j + 1], s2 = g_csr[j + 2], s3 = g_csr[j + 3];
        float w0 = g_dinv[s0] * dd;
        float w1 = g_dinv[s1] * dd;
        float w2 = g_dinv[s2] * dd;
        float w3 = g_dinv[s3] * dd;
        float2 a = __half22float2(hx2[s0 * 32 + lane]);
        float2 b = __half22float2(hx2[s1 * 32 + lane]);
        float2 c = __half22float2(hx2[s2 * 32 + lane]);
        float2 d = __half22float2(hx2[s3 * 32 + lane]);
        ax += a.x * w0 + b.x * w1 + c.x * w2 + d.x * w3;
        ay += a.y * w0 + b.y * w1 + c.y * w2 + d.y * w3;
    }
    for (; j < end; ++j) {
        int s0 = g_csr[j];
        float w0 = g_dinv[s0] * dd;
        float2 v = __half22float2(hx2[s0 * 32 + lane]);
        ax += v.x * w0;
        ay += v.y * w0;
    }
    float2 o;
    o.x = fmaxf(ax + b_gcn[2 * lane],     0.f);
    o.y = fmaxf(ay + b_gcn[2 * lane + 1], 0.f);
    ((float2*)(g_h1 + (size_t)warp * HID))[lane] = o;
}

// ---------------- GEMM 2: hg = h1 @ W_gat (50000x64 @ 64x256), dual write ---
__global__ void gemm2_kernel(const float* __restrict__ Wg) {
    __shared__ float Wsh[64 * 128];         // 32 KB (half the columns)
    __shared__ float rsh[4 * 64];
    int tid = threadIdx.x;                  // 128
    int colOff = blockIdx.y * 128;
    for (int q = tid; q < 64 * 128; q += 128) {
        int k = q >> 7, c = q & 127;
        Wsh[q] = Wg[k * F2 + colOff + c];
    }
    __syncthreads();
    int rowBase = blockIdx.x * 64;
    for (int r0 = 0; r0 < 64; r0 += 4) {
        for (int q = tid; q < 256; q += 128) {
            int rr = q >> 6, kk = q & 63;
            int row = rowBase + r0 + rr;
            rsh[q] = (row < NN) ? g_h1[(size_t)row * HID + kk] : 0.f;
        }
        __syncthreads();
        float a0 = 0.f, a1 = 0.f, a2 = 0.f, a3 = 0.f;
#pragma unroll
        for (int k = 0; k < 64; ++k) {
            float w = Wsh[k * 128 + tid];
            a0 += rsh[k]       * w;
            a1 += rsh[64 + k]  * w;
            a2 += rsh[128 + k] * w;
            a3 += rsh[192 + k] * w;
        }
        int row = rowBase + r0;
        if (row < NN) {
            size_t p = (size_t)row * F2 + colOff + tid;
            g_hg[p] = a0;  g_hgh[p] = __float2half(a0);
        }
        if (row + 1 < NN) {
            size_t p = (size_t)(row + 1) * F2 + colOff + tid;
            g_hg[p] = a1;  g_hgh[p] = __float2half(a1);
        }
        if (row + 2 < NN) {
            size_t p = (size_t)(row + 2) * F2 + colOff + tid;
            g_hg[p] = a2;  g_hgh[p] = __float2half(a2);
        }
        if (row + 3 < NN) {
            size_t p = (size_t)(row + 3) * F2 + colOff + tid;
            g_hg[p] = a3;  g_hgh[p] = __float2half(a3);
        }
        __syncthreads();
    }
}

// ---------------- attention dot products (from fp32 hg) ---------------------
__global__ void attdot_kernel(const float* __restrict__ att_src,
                              const float* __restrict__ att_dst) {
    __shared__ float ash[F2], adh[F2];
    int tid = threadIdx.x;                  // 256
    ash[tid] = att_src[tid];
    adh[tid] = att_dst[tid];
    __syncthreads();
    int t = blockIdx.x * blockDim.x + tid;
    if (t >= NN * HEADS) return;
    int n = t >> 2, h = t & 3;
    const float4* row = (const float4*)(g_hg + (size_t)n * F2 + h * HID);
    float ss = 0.f, sd = 0.f;
#pragma unroll
    for (int i = 0; i < 16; ++i) {
        float4 v = row[i];
        int c = h * HID + i * 4;
        ss += v.x * ash[c] + v.y * ash[c + 1] + v.z * ash[c + 2] + v.w * ash[c + 3];
        sd += v.x * adh[c] + v.y * adh[c + 1] + v.z * adh[c + 2] + v.w * adh[c + 3];
    }
    g_as[t] = ss;
    g_ad[t] = sd;
}

// ---------------- per-head global maxes of a_s and a_d ----------------------
__global__ void maxhead_kernel() {
    __shared__ float shs[256], shd[256];
    int tid = threadIdx.x;
    int i   = blockIdx.x * 256 + tid;
    float vs = -3.0e38f, vd = -3.0e38f;
    if (i < NN * HEADS) { vs = g_as[i]; vd = g_ad[i]; }
    shs[tid] = vs; shd[tid] = vd;
    __syncthreads();
#pragma unroll
    for (int off = 128; off >= 4; off >>= 1) {   // offsets stay multiples of 4
        if (tid < off) {
            shs[tid] = fmaxf(shs[tid], shs[tid + off]);
            shd[tid] = fmaxf(shd[tid], shd[tid + off]);
        }
        __syncthreads();
    }
    if (tid < 4) {
        atomicMax(&g_maxenc[tid],     fenc(shs[tid]));
        atomicMax(&g_maxenc[4 + tid], fenc(shd[tid]));
    }
}

__device__ __forceinline__ float lrelu(float e) {
    return (e > 0.f) ? e : 0.2f * e;
}

// ---------------- GAT aggregation: one warp per (dst, head) -----------------
// Each warp gathers 128B (one L2 line) per edge; chain-free global-M softmax.
__global__ void gat_agg_kernel(const float* __restrict__ b_gat) {
    int gt   = blockIdx.x * blockDim.x + threadIdx.x;
    int w    = gt >> 5;                     // (dst, head) index
    if (w >= NN * HEADS) return;
    int node = w >> 2;
    int hd   = w & 3;
    int lane = gt & 31;
    float adv = g_ad[node * HEADS + hd];
    float M = lrelu(fdec(g_maxenc[hd]) + fdec(g_maxenc[4 + hd]));
    int beg = g_rowptr[node], end = g_rowptr[node + 1];
    const __half2* tab = (const __half2*)g_hgh;   // row stride = 128 half2
    int off = hd * 32 + lane;                     // half2 offset within row
    float ax = 0.f, ay = 0.f, s = 0.f;

    int j = beg;
    for (; j + 4 <= end; j += 4) {
        int s0 = g_csr[j], s1 = g_csr[j + 1], s2 = g_csr[j + 2], s3 = g_csr[j + 3];
        float w0 = __expf(lrelu(g_as[s0 * HEADS + hd] + adv) - M);
        float w1 = __expf(lrelu(g_as[s1 * HEADS + hd] + adv) - M);
        float w2 = __expf(lrelu(g_as[s2 * HEADS + hd] + adv) - M);
        float w3 = __expf(lrelu(g_as[s3 * HEADS + hd] + adv) - M);
        __half2 v0 = tab[s0 * 128 + off];
        __half2 v1 = tab[s1 * 128 + off];
        __half2 v2 = tab[s2 * 128 + off];
        __half2 v3 = tab[s3 * 128 + off];
        s += w0 + w1 + w2 + w3;
        float2 f0 = __half22float2(v0);
        float2 f1 = __half22float2(v1);
        float2 f2 = __half22float2(v2);
        float2 f3 = __half22float2(v3);
        ax += w0 * f0.x + w1 * f1.x + w2 * f2.x + w3 * f3.x;
        ay += w0 * f0.y + w1 * f1.y + w2 * f2.y + w3 * f3.y;
    }
    for (; j < end; ++j) {
        int s0 = g_csr[j];
        float w0 = __expf(lrelu(g_as[s0 * HEADS + hd] + adv) - M);
        float2 f0 = __half22float2(tab[s0 * 128 + off]);
        s += w0;
        ax += w0 * f0.x;
        ay += w0 * f0.y;
    }
    float inv = 1.f / s;
    int col = hd * HID + lane * 2;
    float2 o;
    o.x = fmaxf(ax * inv + b_gat[col],     0.f);
    o.y = fmaxf(ay * inv + b_gat[col + 1], 0.f);
    *(float2*)(g_out2 + (size_t)node * F2 + col) = o;
}

// ---------------- GEMM 3: out = out2 @ W_fc + b_fc (50000x256 @ 256x32) -----
__global__ void gemm3_kernel(const float* __restrict__ Wfc,
                             const float* __restrict__ bfc,
                             float* __restrict__ out) {
    __shared__ float Wsh[F2 * DOUT];        // 32 KB
    __shared__ float insh[8 * F2];          //  8 KB
    int tid = threadIdx.x;                  // 256
    for (int q = tid; q < F2 * DOUT; q += 256) Wsh[q] = Wfc[q];
    __syncthreads();
    int rowBase = blockIdx.x * 128;
    int r = tid >> 5, c = tid & 31;
    float bv = bfc[c];
    for (int g = 0; g < 128; g += 8) {
        for (int q = tid; q < 8 * F2; q += 256) {
            int rr = q >> 8, kk = q & 255;
            int row = rowBase + g + rr;
            insh[q] = (row < NN) ? g_out2[(size_t)row * F2 + kk] : 0.f;
        }
        __syncthreads();
        float a = 0.f;
#pragma unroll 8
        for (int k = 0; k < F2; ++k) a += insh[r * F2 + k] * Wsh[k * DOUT + c];
        int row = rowBase + g + r;
        if (row < NN) out[row * DOUT + c] = a + bv;
        __syncthreads();
    }
}

// ---------------- launch ----------------------------------------------------
extern "C" void kernel_launch(void* const* d_in, const int* in_sizes, int n_in,
                              void* d_out, int out_size) {
    const float* x       = (const float*)d_in[0];
    const int*   ei      = (const int*)  d_in[1];   // int32 (JAX x64 off)
    const float* W_gcn   = (const float*)d_in[2];
    const float* b_gcn   = (const float*)d_in[3];
    const float* W_gat   = (const float*)d_in[4];
    const float* att_src = (const float*)d_in[5];
    const float* att_dst = (const float*)d_in[6];
    const float* b_gat   = (const float*)d_in[7];
    const float* W_fc    = (const float*)d_in[8];
    const float* b_fc    = (const float*)d_in[9];
    float*       out     = (float*)d_out;

    init_kernel    <<<(NN + 255) / 256, 256>>>();
    deg_kernel     <<<(EE + 255) / 256, 256>>>(ei);
    scan_kernel    <<<1, 1024>>>();
    csr_fill_kernel<<<(ET + 255) / 256, 256>>>(ei);

    gemm1_kernel   <<<(NN * 32 + 255) / 256, 256>>>(x, W_gcn);
    gcn_agg_kernel <<<(NN * 32 + 255) / 256, 256>>>(b_gcn);

    gemm2_kernel   <<<dim3((NN + 63) / 64, 2), 128>>>(W_gat);
    attdot_kernel  <<<(NN * HEADS + 255) / 256, 256>>>(att_src, att_dst);
    maxhead_kernel <<<(NN * HEADS + 255) / 256, 256>>>();
    gat_agg_kernel <<<(NN * HEADS * 32 + 255) / 256, 256>>>(b_gat);

    gemm3_kernel   <<<(NN + 127) / 128, 256>>>(W_fc, b_fc, out);
}

// round 8
// speedup vs baseline: 1.1813x; 1.1813x over previous
#include <cuda_runtime.h>
#include <cuda_fp16.h>

// Problem constants (fixed by the dataset)
constexpr int NN   = 50000;
constexpr int EE   = 1600000;
constexpr int ET   = EE + NN;     // edges + self loops
constexpr int DIN  = 32;
constexpr int HID  = 64;
constexpr int HEADS= 4;
constexpr int F2   = HEADS * HID; // 256
constexpr int DOUT = 32;

// ---------------- scratch (device globals; no allocation allowed) -----------
__device__ __half   g_hx [NN * HID];   // x @ W_gcn  (half gather table)
__device__ float    g_h1 [NN * HID];   // relu(gcn)
__device__ float    g_hg [NN * F2];    // h1 @ W_gat (fp32, for attdot)
__device__ __half   g_hgh[NN * F2];    // h1 @ W_gat (half gather table)
__device__ float    g_out2[NN * F2];   // relu(gat)
__device__ float    g_as [NN * HEADS];
__device__ float    g_ad [NN * HEADS];
__device__ unsigned g_maxenc[2 * HEADS]; // [0..3]=max a_s, [4..7]=max a_d
__device__ float    g_dinv[NN];
__device__ int      g_deg [NN];
__device__ int      g_rowptr[NN + 1];
__device__ int      g_pos [EE];        // position of edge within its dst row
__device__ int      g_csr [ET];

// order-preserving float <-> uint encoding for atomicMax
__device__ __forceinline__ unsigned fenc(float f) {
    unsigned b = __float_as_uint(f);
    return (b & 0x80000000u) ? ~b : (b | 0x80000000u);
}
__device__ __forceinline__ float fdec(unsigned u) {
    return (u & 0x80000000u) ? __uint_as_float(u & 0x7fffffffu)
                             : __uint_as_float(~u);
}

// ---------------- CSR build -------------------------------------------------
__global__ void init_kernel() {
    int i = blockIdx.x * blockDim.x + threadIdx.x;
    if (i < NN) g_deg[i] = 0;
    if (i < 2 * HEADS) g_maxenc[i] = 0u;   // minimum key
}

__global__ void deg_kernel(const int* __restrict__ ei) {
    int i = blockIdx.x * blockDim.x + threadIdx.x;
    if (i >= EE) return;
    int d = ei[EE + i];
    d = min(max(d, 0), NN - 1);
    g_pos[i] = atomicAdd(&g_deg[d], 1);    // position within row; no 2nd atomic later
}

// single-block exclusive scan over (deg+1) -> rowptr; also dinv
__global__ void scan_kernel() {
    __shared__ int sh[1024];
    const int C = 49;                       // 1024*49 >= NN
    int t = threadIdx.x;
    int start = t * C;
    int end   = min(start + C, NN);
    int sum = 0;
    for (int i = start; i < end; ++i) sum += g_deg[i] + 1;
    sh[t] = sum;
    __syncthreads();
    for (int off = 1; off < 1024; off <<= 1) {
        int v = (t >= off) ? sh[t - off] : 0;
        __syncthreads();
        sh[t] += v;
        __syncthreads();
    }
    int run = sh[t] - sum;                  // exclusive prefix
    for (int i = start; i < end; ++i) {
        g_rowptr[i] = run;
        int d = g_deg[i] + 1;
        g_dinv[i] = rsqrtf((float)d);
        run += d;
    }
    if (t == 1023) g_rowptr[NN] = sh[1023];
}

// plain scatter: edge -> rowptr[dst]+pos ; self-loop at rowptr[dst+1]-1
__global__ void csr_fill_kernel(const int* __restrict__ ei) {
    int i = blockIdx.x * blockDim.x + threadIdx.x;
    if (i >= ET) return;
    if (i < EE) {
        int src = min(max(ei[i], 0), NN - 1);
        int dst = min(max(ei[EE + i], 0), NN - 1);
        g_csr[g_rowptr[dst] + g_pos[i]] = src;
    } else {
        int node = i - EE;
        g_csr[g_rowptr[node + 1] - 1] = node;
    }
}

// ---------------- GEMM 1: hx = x @ W_gcn  (50000x32 @ 32x64), half out ------
__global__ void gemm1_kernel(const float* __restrict__ x,
                             const float* __restrict__ W) {
    __shared__ float Wsh[DIN * HID];        // 8 KB
    for (int i = threadIdx.x; i < DIN * HID; i += blockDim.x) Wsh[i] = W[i];
    __syncthreads();
    int gt   = blockIdx.x * blockDim.x + threadIdx.x;
    int warp = gt >> 5;
    int lane = gt & 31;
    if (warp >= NN) return;
    float xv = x[warp * DIN + lane];
    float a0 = 0.f, a1 = 0.f;
#pragma unroll
    for (int k = 0; k < 32; ++k) {
        float xk = __shfl_sync(0xffffffffu, xv, k);
        a0 += xk * Wsh[k * HID + lane];
        a1 += xk * Wsh[k * HID + 32 + lane];
    }
    g_hx[warp * HID + lane]      = __float2half(a0);
    g_hx[warp * HID + 32 + lane] = __float2half(a1);
}

// ---------------- GCN aggregation: warp per dst, half gathers, unroll 2 -----
__global__ void gcn_agg_kernel(const float* __restrict__ b_gcn) {
    int gt   = blockIdx.x * blockDim.x + threadIdx.x;
    int warp = gt >> 5;
    if (warp >= NN) return;
    int lane = gt & 31;
    int beg = g_rowptr[warp], end = g_rowptr[warp + 1];
    float dd = g_dinv[warp];
    float ax = 0.f, ay = 0.f;
    const __half2* hx2 = (const __half2*)g_hx;
    int j = beg;
    for (; j + 2 <= end; j += 2) {
        int s0 = g_csr[j], s1 = g_csr[j + 1];
        float w0 = g_dinv[s0] * dd;
        float w1 = g_dinv[s1] * dd;
        float2 a = __half22float2(hx2[s0 * 32 + lane]);
        float2 b = __half22float2(hx2[s1 * 32 + lane]);
        ax += a.x * w0 + b.x * w1;
        ay += a.y * w0 + b.y * w1;
    }
    if (j < end) {
        int s0 = g_csr[j];
        float w0 = g_dinv[s0] * dd;
        float2 a = __half22float2(hx2[s0 * 32 + lane]);
        ax += a.x * w0;
        ay += a.y * w0;
    }
    float2 o;
    o.x = fmaxf(ax + b_gcn[2 * lane],     0.f);
    o.y = fmaxf(ay + b_gcn[2 * lane + 1], 0.f);
    ((float2*)(g_h1 + (size_t)warp * HID))[lane] = o;
}

// ---------------- GEMM 2: hg = h1 @ W_gat (50000x64 @ 64x256), dual write ---
__global__ void gemm2_kernel(const float* __restrict__ Wg) {
    __shared__ float Wsh[64 * 128];         // 32 KB (half the columns)
    __shared__ float rsh[4 * 64];
    int tid = threadIdx.x;                  // 128
    int colOff = blockIdx.y * 128;
    for (int q = tid; q < 64 * 128; q += 128) {
        int k = q >> 7, c = q & 127;
        Wsh[q] = Wg[k * F2 + colOff + c];
    }
    __syncthreads();
    int rowBase = blockIdx.x * 64;
    for (int r0 = 0; r0 < 64; r0 += 4) {
        for (int q = tid; q < 256; q += 128) {
            int rr = q >> 6, kk = q & 63;
            int row = rowBase + r0 + rr;
            rsh[q] = (row < NN) ? g_h1[(size_t)row * HID + kk] : 0.f;
        }
        __syncthreads();
        float a0 = 0.f, a1 = 0.f, a2 = 0.f, a3 = 0.f;
#pragma unroll
        for (int k = 0; k < 64; ++k) {
            float w = Wsh[k * 128 + tid];
            a0 += rsh[k]       * w;
            a1 += rsh[64 + k]  * w;
            a2 += rsh[128 + k] * w;
            a3 += rsh[192 + k] * w;
        }
        int row = rowBase + r0;
        if (row < NN) {
            size_t p = (size_t)row * F2 + colOff + tid;
            g_hg[p] = a0;  g_hgh[p] = __float2half(a0);
        }
        if (row + 1 < NN) {
            size_t p = (size_t)(row + 1) * F2 + colOff + tid;
            g_hg[p] = a1;  g_hgh[p] = __float2half(a1);
        }
        if (row + 2 < NN) {
            size_t p = (size_t)(row + 2) * F2 + colOff + tid;
            g_hg[p] = a2;  g_hgh[p] = __float2half(a2);
        }
        if (row + 3 < NN) {
            size_t p = (size_t)(row + 3) * F2 + colOff + tid;
            g_hg[p] = a3;  g_hgh[p] = __float2half(a3);
        }
        __syncthreads();
    }
}

// ---------------- attention dot products (from fp32 hg) ---------------------
__global__ void attdot_kernel(const float* __restrict__ att_src,
                              const float* __restrict__ att_dst) {
    __shared__ float ash[F2], adh[F2];
    int tid = threadIdx.x;                  // 256
    ash[tid] = att_src[tid];
    adh[tid] = att_dst[tid];
    __syncthreads();
    int t = blockIdx.x * blockDim.x + tid;
    if (t >= NN * HEADS) return;
    int n = t >> 2, h = t & 3;
    const float4* row = (const float4*)(g_hg + (size_t)n * F2 + h * HID);
    float ss = 0.f, sd = 0.f;
#pragma unroll
    for (int i = 0; i < 16; ++i) {
        float4 v = row[i];
        int c = h * HID + i * 4;
        ss += v.x * ash[c] + v.y * ash[c + 1] + v.z * ash[c + 2] + v.w * ash[c + 3];
        sd += v.x * adh[c] + v.y * adh[c + 1] + v.z * adh[c + 2] + v.w * adh[c + 3];
    }
    g_as[t] = ss;
    g_ad[t] = sd;
}

// ---------------- per-head global maxes of a_s and a_d ----------------------
__global__ void maxhead_kernel() {
    __shared__ float shs[256], shd[256];
    int tid = threadIdx.x;
    int i   = blockIdx.x * 256 + tid;
    float vs = -3.0e38f, vd = -3.0e38f;
    if (i < NN * HEADS) { vs = g_as[i]; vd = g_ad[i]; }
    shs[tid] = vs; shd[tid] = vd;
    __syncthreads();
#pragma unroll
    for (int off = 128; off >= 4; off >>= 1) {   // offsets stay multiples of 4
        if (tid < off) {
            shs[tid] = fmaxf(shs[tid], shs[tid + off]);
            shd[tid] = fmaxf(shd[tid], shd[tid + off]);
        }
        __syncthreads();
    }
    if (tid < 4) {
        atomicMax(&g_maxenc[tid],     fenc(shs[tid]));
        atomicMax(&g_maxenc[4 + tid], fenc(shd[tid]));
    }
}

__device__ __forceinline__ float lrelu(float e) {
    return (e > 0.f) ? e : 0.2f * e;
}

// ---------------- GAT aggregation: warp per dst, chain-free, unroll 2 -------
// R3's exact memory/register shape, but softmax uses the global per-head
// bound M (exact: shift invariance) so there is no loop-carried rescale.
__global__ void gat_agg_kernel(const float* __restrict__ b_gat) {
    int gt   = blockIdx.x * blockDim.x + threadIdx.x;
    int warp = gt >> 5;
    if (warp >= NN) return;
    int lane = gt & 31;
    int hd   = lane >> 3;                   // head for this lane
    int base = hd * HID + (lane & 7) * 8;   // 8 contiguous features
    float adv = g_ad[warp * HEADS + hd];
    float M = lrelu(fdec(g_maxenc[hd]) + fdec(g_maxenc[4 + hd]));
    int beg = g_rowptr[warp], end = g_rowptr[warp + 1];
    float s = 0.f;
    float acc[8];
#pragma unroll
    for (int k = 0; k < 8; ++k) acc[k] = 0.f;

    int j = beg;
    for (; j + 2 <= end; j += 2) {
        int s0 = g_csr[j], s1 = g_csr[j + 1];
        float w0 = __expf(lrelu(g_as[s0 * HEADS + hd] + adv) - M);
        float w1 = __expf(lrelu(g_as[s1 * HEADS + hd] + adv) - M);
        int4 p0 = *(const int4*)(g_hgh + (size_t)s0 * F2 + base);
        int4 p1 = *(const int4*)(g_hgh + (size_t)s1 * F2 + base);
        s += w0 + w1;
        const __half2* h0 = (const __half2*)&p0;
        const __half2* h1 = (const __half2*)&p1;
#pragma unroll
        for (int k = 0; k < 4; ++k) {
            float2 a = __half22float2(h0[k]);
            float2 b = __half22float2(h1[k]);
            acc[2 * k]     += w0 * a.x + w1 * b.x;
            acc[2 * k + 1] += w0 * a.y + w1 * b.y;
        }
    }
    if (j < end) {
        int s0 = g_csr[j];
        float w0 = __expf(lrelu(g_as[s0 * HEADS + hd] + adv) - M);
        int4 p0 = *(const int4*)(g_hgh + (size_t)s0 * F2 + base);
        const __half2* h0 = (const __half2*)&p0;
        s += w0;
#pragma unroll
        for (int k = 0; k < 4; ++k) {
            float2 a = __half22float2(h0[k]);
            acc[2 * k]     += w0 * a.x;
            acc[2 * k + 1] += w0 * a.y;
        }
    }
    float inv = 1.f / s;
    float* o = g_out2 + (size_t)warp * F2 + base;
#pragma unroll
    for (int k = 0; k < 8; ++k)
        o[k] = fmaxf(acc[k] * inv + b_gat[base + k], 0.f);
}

// ---------------- GEMM 3: out = out2 @ W_fc + b_fc (50000x256 @ 256x32) -----
__global__ void gemm3_kernel(const float* __restrict__ Wfc,
                             const float* __restrict__ bfc,
                             float* __restrict__ out) {
    __shared__ float Wsh[F2 * DOUT];        // 32 KB
    __shared__ float insh[8 * F2];          //  8 KB
    int tid = threadIdx.x;                  // 256
    for (int q = tid; q < F2 * DOUT; q += 256) Wsh[q] = Wfc[q];
    __syncthreads();
    int rowBase = blockIdx.x * 128;
    int r = tid >> 5, c = tid & 31;
    float bv = bfc[c];
    for (int g = 0; g < 128; g += 8) {
        for (int q = tid; q < 8 * F2; q += 256) {
            int rr = q >> 8, kk = q & 255;
            int row = rowBase + g + rr;
            insh[q] = (row < NN) ? g_out2[(size_t)row * F2 + kk] : 0.f;
        }
        __syncthreads();
        float a = 0.f;
#pragma unroll 8
        for (int k = 0; k < F2; ++k) a += insh[r * F2 + k] * Wsh[k * DOUT + c];
        int row = rowBase + g + r;
        if (row < NN) out[row * DOUT + c] = a + bv;
        __syncthreads();
    }
}

// ---------------- launch ----------------------------------------------------
extern "C" void kernel_launch(void* const* d_in, const int* in_sizes, int n_in,
                              void* d_out, int out_size) {
    const float* x       = (const float*)d_in[0];
    const int*   ei      = (const int*)  d_in[1];   // int32 (JAX x64 off)
    const float* W_gcn   = (const float*)d_in[2];
    const float* b_gcn   = (const float*)d_in[3];
    const float* W_gat   = (const float*)d_in[4];
    const float* att_src = (const float*)d_in[5];
    const float* att_dst = (const float*)d_in[6];
    const float* b_gat   = (const float*)d_in[7];
    const float* W_fc    = (const float*)d_in[8];
    const float* b_fc    = (const float*)d_in[9];
    float*       out     = (float*)d_out;

    init_kernel    <<<(NN + 255) / 256, 256>>>();
    deg_kernel     <<<(EE + 255) / 256, 256>>>(ei);
    scan_kernel    <<<1, 1024>>>();
    csr_fill_kernel<<<(ET + 255) / 256, 256>>>(ei);

    gemm1_kernel   <<<(NN * 32 + 255) / 256, 256>>>(x, W_gcn);
    gcn_agg_kernel <<<(NN * 32 + 255) / 256, 256>>>(b_gcn);

    gemm2_kernel   <<<dim3((NN + 63) / 64, 2), 128>>>(W_gat);
    attdot_kernel  <<<(NN * HEADS + 255) / 256, 256>>>(att_src, att_dst);
    maxhead_kernel <<<(NN * HEADS + 255) / 256, 256>>>();
    gat_agg_kernel <<<(NN * 32 + 255) / 256, 256>>>(b_gat);

    gemm3_kernel   <<<(NN + 127) / 128, 256>>>(W_fc, b_fc, out);
}

// round 9
// speedup vs baseline: 1.4567x; 1.2331x over previous
#include <cuda_runtime.h>
#include <cuda_fp16.h>

// Problem constants (fixed by the dataset)
constexpr int NN   = 50000;
constexpr int EE   = 1600000;
constexpr int ET   = EE + NN;     // edges + self loops
constexpr int DIN  = 32;
constexpr int HID  = 64;
constexpr int HEADS= 4;
constexpr int F2   = HEADS * HID; // 256
constexpr int DOUT = 32;
constexpr int NB   = (NN + 255) / 256;   // 196 blocks for scan

// ---------------- scratch (device globals; no allocation allowed) -----------
__device__ __half g_hx [NN * HID];   // x @ W_gcn  (half gather table)
__device__ float  g_h1 [NN * HID];   // relu(gcn)
__device__ __half g_hgh[NN * F2];    // h1 @ W_gat (half gather table)
__device__ float  g_out2[NN * F2];   // relu(gat)
__device__ float  g_as [NN * HEADS];
__device__ float  g_ad [NN * HEADS];
__device__ float  g_dinv[NN];
__device__ int    g_deg [NN];
__device__ int    g_rowptr[NN + 1];
__device__ int    g_bsum[NB];
__device__ int    g_boff[NB];
__device__ int    g_pos [EE];        // position of edge within its dst row
__device__ int    g_csr [ET];

// ---------------- CSR build -------------------------------------------------
__global__ void init_kernel() {
    int i = blockIdx.x * blockDim.x + threadIdx.x;
    if (i < NN) g_deg[i] = 0;
}

__global__ void deg_kernel(const int* __restrict__ ei) {
    int i = blockIdx.x * blockDim.x + threadIdx.x;
    if (i >= EE) return;
    int d = ei[EE + i];
    d = min(max(d, 0), NN - 1);
    g_pos[i] = atomicAdd(&g_deg[d], 1);    // position within row; no 2nd atomic later
}

// two-level scan over (deg+1): block partials, tiny scan, per-block fill
__global__ void scan_partial_kernel() {
    __shared__ int sh[256];
    int t = threadIdx.x, b = blockIdx.x;
    int i = b * 256 + t;
    int v = (i < NN) ? g_deg[i] + 1 : 0;
    sh[t] = v;
    __syncthreads();
#pragma unroll
    for (int off = 128; off > 0; off >>= 1) {
        if (t < off) sh[t] += sh[t + off];
        __syncthreads();
    }
    if (t == 0) g_bsum[b] = sh[0];
}

__global__ void scan_block_kernel() {      // 1 block, 256 threads
    __shared__ int sh[256];
    int t = threadIdx.x;
    int v = (t < NB) ? g_bsum[t] : 0;
    sh[t] = v;
    __syncthreads();
    for (int off = 1; off < 256; off <<= 1) {
        int u = (t >= off) ? sh[t - off] : 0;
        __syncthreads();
        sh[t] += u;
        __syncthreads();
    }
    if (t < NB) g_boff[t] = sh[t] - v;     // exclusive
}

__global__ void rowptr_kernel() {
    __shared__ int sh[256];
    int t = threadIdx.x, b = blockIdx.x;
    int i = b * 256 + t;
    int v = (i < NN) ? g_deg[i] + 1 : 0;
    sh[t] = v;
    __syncthreads();
    for (int off = 1; off < 256; off <<= 1) {
        int u = (t >= off) ? sh[t - off] : 0;
        __syncthreads();
        sh[t] += u;
        __syncthreads();
    }
    int excl = sh[t] - v + g_boff[b];
    if (i < NN) {
        g_rowptr[i] = excl;
        g_dinv[i] = rsqrtf((float)v);
        if (i == NN - 1) g_rowptr[NN] = excl + v;
    }
}

// plain scatter: edge -> rowptr[dst]+pos ; self-loop at rowptr[dst+1]-1
__global__ void csr_fill_kernel(const int* __restrict__ ei) {
    int i = blockIdx.x * blockDim.x + threadIdx.x;
    if (i >= ET) return;
    if (i < EE) {
        int src = min(max(ei[i], 0), NN - 1);
        int dst = min(max(ei[EE + i], 0), NN - 1);
        g_csr[g_rowptr[dst] + g_pos[i]] = src;
    } else {
        int node = i - EE;
        g_csr[g_rowptr[node + 1] - 1] = node;
    }
}

// ---------------- GEMM 1: hx = x @ W_gcn  (50000x32 @ 32x64), half out ------
__global__ void gemm1_kernel(const float* __restrict__ x,
                             const float* __restrict__ W) {
    __shared__ float Wsh[DIN * HID];        // 8 KB
    for (int i = threadIdx.x; i < DIN * HID; i += blockDim.x) Wsh[i] = W[i];
    __syncthreads();
    int gt   = blockIdx.x * blockDim.x + threadIdx.x;
    int warp = gt >> 5;
    int lane = gt & 31;
    if (warp >= NN) return;
    float xv = x[warp * DIN + lane];
    float a0 = 0.f, a1 = 0.f;
#pragma unroll
    for (int k = 0; k < 32; ++k) {
        float xk = __shfl_sync(0xffffffffu, xv, k);
        a0 += xk * Wsh[k * HID + lane];
        a1 += xk * Wsh[k * HID + 32 + lane];
    }
    g_hx[warp * HID + lane]      = __float2half(a0);
    g_hx[warp * HID + 32 + lane] = __float2half(a1);
}

// ---------------- GCN aggregation: warp per dst, half gathers, unroll 2 -----
__global__ void gcn_agg_kernel(const float* __restrict__ b_gcn) {
    int gt   = blockIdx.x * blockDim.x + threadIdx.x;
    int warp = gt >> 5;
    if (warp >= NN) return;
    int lane = gt & 31;
    int beg = g_rowptr[warp], end = g_rowptr[warp + 1];
    float dd = g_dinv[warp];
    float ax = 0.f, ay = 0.f;
    const __half2* hx2 = (const __half2*)g_hx;
    int j = beg;
    for (; j + 2 <= end; j += 2) {
        int s0 = g_csr[j], s1 = g_csr[j + 1];
        float w0 = g_dinv[s0] * dd;
        float w1 = g_dinv[s1] * dd;
        float2 a = __half22float2(hx2[s0 * 32 + lane]);
        float2 b = __half22float2(hx2[s1 * 32 + lane]);
        ax += a.x * w0 + b.x * w1;
        ay += a.y * w0 + b.y * w1;
    }
    if (j < end) {
        int s0 = g_csr[j];
        float w0 = g_dinv[s0] * dd;
        float2 a = __half22float2(hx2[s0 * 32 + lane]);
        ax += a.x * w0;
        ay += a.y * w0;
    }
    float2 o;
    o.x = fmaxf(ax + b_gcn[2 * lane],     0.f);
    o.y = fmaxf(ay + b_gcn[2 * lane + 1], 0.f);
    ((float2*)(g_h1 + (size_t)warp * HID))[lane] = o;
}

// ---------------- GEMM 2 + block-local attention dots (no atomics) ----------
// hg = h1 @ W_gat (50000x64 @ 64x256). Block covers 128 cols = 2 whole heads,
// so a_s/a_d per (row, head) reduce inside the block: warp shfl + smem.
__global__ void gemm2_kernel(const float* __restrict__ Wg,
                             const float* __restrict__ att_src,
                             const float* __restrict__ att_dst) {
    __shared__ float Wsh[64 * 128];         // 32 KB (half the columns)
    __shared__ float rsh[4 * 64];
    __shared__ float ash[128], adh[128];
    __shared__ float red[4][4][2];          // [warp][row][s|d]
    int tid = threadIdx.x;                  // 128
    int colOff = blockIdx.y * 128;
    ash[tid] = att_src[colOff + tid];
    adh[tid] = att_dst[colOff + tid];
    for (int q = tid; q < 64 * 128; q += 128) {
        int k = q >> 7, c = q & 127;
        Wsh[q] = Wg[k * F2 + colOff + c];
    }
    __syncthreads();
    int lane = tid & 31, warp = tid >> 5;
    int rowBase = blockIdx.x * 64;
    for (int r0 = 0; r0 < 64; r0 += 4) {
        for (int q = tid; q < 256; q += 128) {
            int rr = q >> 6, kk = q & 63;
            int row = rowBase + r0 + rr;
            rsh[q] = (row < NN) ? g_h1[(size_t)row * HID + kk] : 0.f;
        }
        __syncthreads();
        float a0 = 0.f, a1 = 0.f, a2 = 0.f, a3 = 0.f;
#pragma unroll
        for (int k = 0; k < 64; ++k) {
            float w = Wsh[k * 128 + tid];
            a0 += rsh[k]       * w;
            a1 += rsh[64 + k]  * w;
            a2 += rsh[128 + k] * w;
            a3 += rsh[192 + k] * w;
        }
        float av[4] = {a0, a1, a2, a3};
#pragma unroll
        for (int rr = 0; rr < 4; ++rr) {
            float vs = av[rr] * ash[tid];
            float vd = av[rr] * adh[tid];
#pragma unroll
            for (int off = 16; off; off >>= 1) {
                vs += __shfl_down_sync(0xffffffffu, vs, off);
                vd += __shfl_down_sync(0xffffffffu, vd, off);
            }
            if (lane == 0) { red[warp][rr][0] = vs; red[warp][rr][1] = vd; }
            int row = rowBase + r0 + rr;
            if (row < NN)
                g_hgh[(size_t)row * F2 + colOff + tid] = __float2half(av[rr]);
        }
        __syncthreads();
        if (tid < 16) {                     // rr(2b) | hl(1b) | sd(1b)
            int rr = tid & 3, hl = (tid >> 2) & 1, sd = tid >> 3;
            int row = rowBase + r0 + rr;
            if (row < NN) {
                float v = red[2 * hl][rr][sd] + red[2 * hl + 1][rr][sd];
                int head = (colOff >> 6) + hl;
                (sd ? g_ad : g_as)[row * HEADS + head] = v;
            }
        }
        __syncthreads();
    }
}

__device__ __forceinline__ float lrelu(float e) {
    return (e > 0.f) ? e : 0.2f * e;
}

// ---------------- GAT aggregation: warp per dst, online softmax (R3) --------
__global__ void gat_agg_kernel(const float* __restrict__ b_gat) {
    int gt   = blockIdx.x * blockDim.x + threadIdx.x;
    int warp = gt >> 5;
    if (warp >= NN) return;
    int lane = gt & 31;
    int hd   = lane >> 3;                   // head for this lane
    int base = hd * HID + (lane & 7) * 8;   // 8 contiguous features
    float adv = g_ad[warp * HEADS + hd];
    int beg = g_rowptr[warp], end = g_rowptr[warp + 1];
    float m = -3.0e38f, s = 0.f;
    float acc[8];
#pragma unroll
    for (int k = 0; k < 8; ++k) acc[k] = 0.f;

    int j = beg;
    for (; j + 2 <= end; j += 2) {
        int s0 = g_csr[j], s1 = g_csr[j + 1];
        float e0 = lrelu(g_as[s0 * HEADS + hd] + adv);
        float e1 = lrelu(g_as[s1 * HEADS + hd] + adv);
        int4 p0 = *(const int4*)(g_hgh + (size_t)s0 * F2 + base);
        int4 p1 = *(const int4*)(g_hgh + (size_t)s1 * F2 + base);
        float nm = fmaxf(m, fmaxf(e0, e1));
        float sc = __expf(m - nm);
        float w0 = __expf(e0 - nm);
        float w1 = __expf(e1 - nm);
        s = s * sc + w0 + w1;
        const __half2* h0 = (const __half2*)&p0;
        const __half2* h1 = (const __half2*)&p1;
#pragma unroll
        for (int k = 0; k < 4; ++k) {
            float2 a = __half22float2(h0[k]);
            float2 b = __half22float2(h1[k]);
            acc[2 * k]     = acc[2 * k]     * sc + w0 * a.x + w1 * b.x;
            acc[2 * k + 1] = acc[2 * k + 1] * sc + w0 * a.y + w1 * b.y;
        }
        m = nm;
    }
    if (j < end) {
        int s0 = g_csr[j];
        float e0 = lrelu(g_as[s0 * HEADS + hd] + adv);
        int4 p0 = *(const int4*)(g_hgh + (size_t)s0 * F2 + base);
        float nm = fmaxf(m, e0);
        float sc = __expf(m - nm);
        float w0 = __expf(e0 - nm);
        s = s * sc + w0;
        const __half2* h0 = (const __half2*)&p0;
#pragma unroll
        for (int k = 0; k < 4; ++k) {
            float2 a = __half22float2(h0[k]);
            acc[2 * k]     = acc[2 * k]     * sc + w0 * a.x;
            acc[2 * k + 1] = acc[2 * k + 1] * sc + w0 * a.y;
        }
    }
    float inv = 1.f / s;
    float* o = g_out2 + (size_t)warp * F2 + base;
#pragma unroll
    for (int k = 0; k < 8; ++k)
        o[k] = fmaxf(acc[k] * inv + b_gat[base + k], 0.f);
}

// ---------------- GEMM 3: out = out2 @ W_fc + b_fc (50000x256 @ 256x32) -----
__global__ void gemm3_kernel(const float* __restrict__ Wfc,
                             const float* __restrict__ bfc,
                             float* __restrict__ out) {
    __shared__ float Wsh[F2 * DOUT];        // 32 KB
    __shared__ float insh[8 * F2];          //  8 KB
    int tid = threadIdx.x;                  // 256
    for (int q = tid; q < F2 * DOUT; q += 256) Wsh[q] = Wfc[q];
    __syncthreads();
    int rowBase = blockIdx.x * 128;
    int r = tid >> 5, c = tid & 31;
    float bv = bfc[c];
    for (int g = 0; g < 128; g += 8) {
        for (int q = tid; q < 8 * F2; q += 256) {
            int rr = q >> 8, kk = q & 255;
            int row = rowBase + g + rr;
            insh[q] = (row < NN) ? g_out2[(size_t)row * F2 + kk] : 0.f;
        }
        __syncthreads();
        float a = 0.f;
#pragma unroll 8
        for (int k = 0; k < F2; ++k) a += insh[r * F2 + k] * Wsh[k * DOUT + c];
        int row = rowBase + g + r;
        if (row < NN) out[row * DOUT + c] = a + bv;
        __syncthreads();
    }
}

// ---------------- launch ----------------------------------------------------
extern "C" void kernel_launch(void* const* d_in, const int* in_sizes, int n_in,
                              void* d_out, int out_size) {
    const float* x       = (const float*)d_in[0];
    const int*   ei      = (const int*)  d_in[1];   // int32 (JAX x64 off)
    const float* W_gcn   = (const float*)d_in[2];
    const float* b_gcn   = (const float*)d_in[3];
    const float* W_gat   = (const float*)d_in[4];
    const float* att_src = (const float*)d_in[5];
    const float* att_dst = (const float*)d_in[6];
    const float* b_gat   = (const float*)d_in[7];
    const float* W_fc    = (const float*)d_in[8];
    const float* b_fc    = (const float*)d_in[9];
    float*       out     = (float*)d_out;

    init_kernel        <<<(NN + 255) / 256, 256>>>();
    deg_kernel         <<<(EE + 255) / 256, 256>>>(ei);
    scan_partial_kernel<<<NB, 256>>>();
    scan_block_kernel  <<<1, 256>>>();
    rowptr_kernel      <<<NB, 256>>>();
    csr_fill_kernel    <<<(ET + 255) / 256, 256>>>(ei);

    gemm1_kernel       <<<(NN * 32 + 255) / 256, 256>>>(x, W_gcn);
    gcn_agg_kernel     <<<(NN * 32 + 255) / 256, 256>>>(b_gcn);

    gemm2_kernel       <<<dim3((NN + 63) / 64, 2), 128>>>(W_gat, att_src, att_dst);
    gat_agg_kernel     <<<(NN * 32 + 255) / 256, 256>>>(b_gat);

    gemm3_kernel       <<<(NN + 127) / 128, 256>>>(W_fc, b_fc, out);
}

// round 10
// speedup vs baseline: 1.6477x; 1.1311x over previous
#include <cuda_runtime.h>
#include <cuda_fp16.h>

// Problem constants (fixed by the dataset)
constexpr int NN   = 50000;
constexpr int EE   = 1600000;
constexpr int ET   = EE + NN;     // edges + self loops
constexpr int DIN  = 32;
constexpr int HID  = 64;
constexpr int HEADS= 4;
constexpr int F2   = HEADS * HID; // 256
constexpr int DOUT = 32;
constexpr int NB   = (NN + 255) / 256;   // 196 blocks for scan

// ---------------- scratch (device globals; no allocation allowed) -----------
__device__ __half g_hx  [NN * HID];  // x @ W_gcn  (half gather table)
__device__ float  g_h1  [NN * HID];  // relu(gcn)
__device__ __half g_hgh [NN * F2];   // h1 @ W_gat (half gather table)
__device__ __half g_out2h[NN * F2];  // relu(gat), half
__device__ float  g_as  [NN * HEADS];
__device__ float  g_ad  [NN * HEADS];
__device__ float  g_dinv[NN];
__device__ int    g_deg [NN];
__device__ int    g_rowptr[NN + 1];
__device__ int    g_bsum[NB];
__device__ int    g_pos [EE];        // position of edge within its dst row
__device__ int    g_csr [ET];

// ---------------- CSR build -------------------------------------------------
__global__ void init_kernel() {
    int i = blockIdx.x * blockDim.x + threadIdx.x;
    if (i < NN) g_deg[i] = 0;
}

__global__ void deg_kernel(const int* __restrict__ ei) {
    int i = blockIdx.x * blockDim.x + threadIdx.x;
    if (i >= EE) return;
    int d = ei[EE + i];
    d = min(max(d, 0), NN - 1);
    g_pos[i] = atomicAdd(&g_deg[d], 1);    // position within row; no 2nd atomic later
}

// block partial sums of (deg+1)
__global__ void scan_partial_kernel() {
    __shared__ int sh[256];
    int t = threadIdx.x, b = blockIdx.x;
    int i = b * 256 + t;
    int v = (i < NN) ? g_deg[i] + 1 : 0;
    sh[t] = v;
    __syncthreads();
#pragma unroll
    for (int off = 128; off > 0; off >>= 1) {
        if (t < off) sh[t] += sh[t + off];
        __syncthreads();
    }
    if (t == 0) g_bsum[b] = sh[0];
}

// rowptr: block offset = reduction of g_bsum[0..b-1], then local scan
__global__ void rowptr_kernel() {
    __shared__ int sh[256];
    __shared__ int boff_sh;
    int t = threadIdx.x, b = blockIdx.x;
    int v0 = (t < b && t < NB) ? g_bsum[t] : 0;
    sh[t] = v0;
    __syncthreads();
#pragma unroll
    for (int off = 128; off > 0; off >>= 1) {
        if (t < off) sh[t] += sh[t + off];
        __syncthreads();
    }
    if (t == 0) boff_sh = sh[0];
    __syncthreads();
    int i = b * 256 + t;
    int v = (i < NN) ? g_deg[i] + 1 : 0;
    sh[t] = v;
    __syncthreads();
    for (int off = 1; off < 256; off <<= 1) {
        int u = (t >= off) ? sh[t - off] : 0;
        __syncthreads();
        sh[t] += u;
        __syncthreads();
    }
    int excl = sh[t] - v + boff_sh;
    if (i < NN) {
        g_rowptr[i] = excl;
        g_dinv[i] = rsqrtf((float)v);
        if (i == NN - 1) g_rowptr[NN] = excl + v;
    }
}

// plain scatter: edge -> rowptr[dst]+pos ; self-loop at rowptr[dst+1]-1
__global__ void csr_fill_kernel(const int* __restrict__ ei) {
    int i = blockIdx.x * blockDim.x + threadIdx.x;
    if (i >= ET) return;
    if (i < EE) {
        int src = min(max(ei[i], 0), NN - 1);
        int dst = min(max(ei[EE + i], 0), NN - 1);
        g_csr[g_rowptr[dst] + g_pos[i]] = src;
    } else {
        int node = i - EE;
        g_csr[g_rowptr[node + 1] - 1] = node;
    }
}

// ---------------- GEMM 1: hx = x @ W_gcn  (50000x32 @ 32x64), half out ------
__global__ void gemm1_kernel(const float* __restrict__ x,
                             const float* __restrict__ W) {
    __shared__ float Wsh[DIN * HID];        // 8 KB
    for (int i = threadIdx.x; i < DIN * HID; i += blockDim.x) Wsh[i] = W[i];
    __syncthreads();
    int gt   = blockIdx.x * blockDim.x + threadIdx.x;
    int warp = gt >> 5;
    int lane = gt & 31;
    if (warp >= NN) return;
    float xv = x[warp * DIN + lane];
    float a0 = 0.f, a1 = 0.f;
#pragma unroll
    for (int k = 0; k < 32; ++k) {
        float xk = __shfl_sync(0xffffffffu, xv, k);
        a0 += xk * Wsh[k * HID + lane];
        a1 += xk * Wsh[k * HID + 32 + lane];
    }
    g_hx[warp * HID + lane]      = __float2half(a0);
    g_hx[warp * HID + 32 + lane] = __float2half(a1);
}

// ---------------- GCN aggregation: warp per dst, half gathers, unroll 2 -----
__global__ void gcn_agg_kernel(const float* __restrict__ b_gcn) {
    int gt   = blockIdx.x * blockDim.x + threadIdx.x;
    int warp = gt >> 5;
    if (warp >= NN) return;
    int lane = gt & 31;
    int beg = g_rowptr[warp], end = g_rowptr[warp + 1];
    float dd = g_dinv[warp];
    float ax = 0.f, ay = 0.f;
    const __half2* hx2 = (const __half2*)g_hx;
    int j = beg;
    for (; j + 2 <= end; j += 2) {
        int s0 = g_csr[j], s1 = g_csr[j + 1];
        float w0 = g_dinv[s0] * dd;
        float w1 = g_dinv[s1] * dd;
        float2 a = __half22float2(hx2[s0 * 32 + lane]);
        float2 b = __half22float2(hx2[s1 * 32 + lane]);
        ax += a.x * w0 + b.x * w1;
        ay += a.y * w0 + b.y * w1;
    }
    if (j < end) {
        int s0 = g_csr[j];
        float w0 = g_dinv[s0] * dd;
        float2 a = __half22float2(hx2[s0 * 32 + lane]);
        ax += a.x * w0;
        ay += a.y * w0;
    }
    float2 o;
    o.x = fmaxf(ax + b_gcn[2 * lane],     0.f);
    o.y = fmaxf(ay + b_gcn[2 * lane + 1], 0.f);
    ((float2*)(g_h1 + (size_t)warp * HID))[lane] = o;
}

// ---------------- GEMM 2 + block-local attention dots (no atomics) ----------
__global__ void gemm2_kernel(const float* __restrict__ Wg,
                             const float* __restrict__ att_src,
                             const float* __restrict__ att_dst) {
    __shared__ float Wsh[64 * 128];         // 32 KB (half the columns)
    __shared__ float rsh[4 * 64];
    __shared__ float ash[128], adh[128];
    __shared__ float red[4][4][2];          // [warp][row][s|d]
    int tid = threadIdx.x;                  // 128
    int colOff = blockIdx.y * 128;
    ash[tid] = att_src[colOff + tid];
    adh[tid] = att_dst[colOff + tid];
    for (int q = tid; q < 64 * 128; q += 128) {
        int k = q >> 7, c = q & 127;
        Wsh[q] = Wg[k * F2 + colOff + c];
    }
    __syncthreads();
    int lane = tid & 31, warp = tid >> 5;
    int rowBase = blockIdx.x * 64;
    for (int r0 = 0; r0 < 64; r0 += 4) {
        for (int q = tid; q < 256; q += 128) {
            int rr = q >> 6, kk = q & 63;
            int row = rowBase + r0 + rr;
            rsh[q] = (row < NN) ? g_h1[(size_t)row * HID + kk] : 0.f;
        }
        __syncthreads();
        float a0 = 0.f, a1 = 0.f, a2 = 0.f, a3 = 0.f;
#pragma unroll
        for (int k = 0; k < 64; ++k) {
            float w = Wsh[k * 128 + tid];
            a0 += rsh[k]       * w;
            a1 += rsh[64 + k]  * w;
            a2 += rsh[128 + k] * w;
            a3 += rsh[192 + k] * w;
        }
        float av[4] = {a0, a1, a2, a3};
#pragma unroll
        for (int rr = 0; rr < 4; ++rr) {
            float vs = av[rr] * ash[tid];
            float vd = av[rr] * adh[tid];
#pragma unroll
            for (int off = 16; off; off >>= 1) {
                vs += __shfl_down_sync(0xffffffffu, vs, off);
                vd += __shfl_down_sync(0xffffffffu, vd, off);
            }
            if (lane == 0) { red[warp][rr][0] = vs; red[warp][rr][1] = vd; }
            int row = rowBase + r0 + rr;
            if (row < NN)
                g_hgh[(size_t)row * F2 + colOff + tid] = __float2half(av[rr]);
        }
        __syncthreads();
        if (tid < 16) {                     // rr(2b) | hl(1b) | sd(1b)
            int rr = tid & 3, hl = (tid >> 2) & 1, sd = tid >> 3;
            int row = rowBase + r0 + rr;
            if (row < NN) {
                float v = red[2 * hl][rr][sd] + red[2 * hl + 1][rr][sd];
                int head = (colOff >> 6) + hl;
                (sd ? g_ad : g_as)[row * HEADS + head] = v;
            }
        }
        __syncthreads();
    }
}

__device__ __forceinline__ float lrelu(float e) {
    return (e > 0.f) ? e : 0.2f * e;
}

// ---------------- GAT aggregation: warp per dst, online softmax (R3) --------
__global__ void gat_agg_kernel(const float* __restrict__ b_gat) {
    int gt   = blockIdx.x * blockDim.x + threadIdx.x;
    int warp = gt >> 5;
    if (warp >= NN) return;
    int lane = gt & 31;
    int hd   = lane >> 3;                   // head for this lane
    int base = hd * HID + (lane & 7) * 8;   // 8 contiguous features
    float adv = g_ad[warp * HEADS + hd];
    int beg = g_rowptr[warp], end = g_rowptr[warp + 1];
    float m = -3.0e38f, s = 0.f;
    float acc[8];
#pragma unroll
    for (int k = 0; k < 8; ++k) acc[k] = 0.f;

    int j = beg;
    for (; j + 2 <= end; j += 2) {
        int s0 = g_csr[j], s1 = g_csr[j + 1];
        float e0 = lrelu(g_as[s0 * HEADS + hd] + adv);
        float e1 = lrelu(g_as[s1 * HEADS + hd] + adv);
        int4 p0 = *(const int4*)(g_hgh + (size_t)s0 * F2 + base);
        int4 p1 = *(const int4*)(g_hgh + (size_t)s1 * F2 + base);
        float nm = fmaxf(m, fmaxf(e0, e1));
        float sc = __expf(m - nm);
        float w0 = __expf(e0 - nm);
        float w1 = __expf(e1 - nm);
        s = s * sc + w0 + w1;
        const __half2* h0 = (const __half2*)&p0;
        const __half2* h1 = (const __half2*)&p1;
#pragma unroll
        for (int k = 0; k < 4; ++k) {
            float2 a = __half22float2(h0[k]);
            float2 b = __half22float2(h1[k]);
            acc[2 * k]     = acc[2 * k]     * sc + w0 * a.x + w1 * b.x;
            acc[2 * k + 1] = acc[2 * k + 1] * sc + w0 * a.y + w1 * b.y;
        }
        m = nm;
    }
    if (j < end) {
        int s0 = g_csr[j];
        float e0 = lrelu(g_as[s0 * HEADS + hd] + adv);
        int4 p0 = *(const int4*)(g_hgh + (size_t)s0 * F2 + base);
        float nm = fmaxf(m, e0);
        float sc = __expf(m - nm);
        float w0 = __expf(e0 - nm);
        s = s * sc + w0;
        const __half2* h0 = (const __half2*)&p0;
#pragma unroll
        for (int k = 0; k < 4; ++k) {
            float2 a = __half22float2(h0[k]);
            acc[2 * k]     = acc[2 * k]     * sc + w0 * a.x;
            acc[2 * k + 1] = acc[2 * k + 1] * sc + w0 * a.y;
        }
    }
    float inv = 1.f / s;
    __half2* o = (__half2*)(g_out2h + (size_t)warp * F2 + base);
#pragma unroll
    for (int k = 0; k < 4; ++k) {
        float vx = fmaxf(acc[2 * k]     * inv + b_gat[base + 2 * k],     0.f);
        float vy = fmaxf(acc[2 * k + 1] * inv + b_gat[base + 2 * k + 1], 0.f);
        o[k] = __floats2half2_rn(vx, vy);
    }
}

// ---------------- GEMM 3: out = out2h @ W_fc + b_fc (50000x256 @ 256x32) ----
// Register-tiled: 4 rows per thread, 32-row groups; half input, fp32 W.
__global__ void gemm3_kernel(const float* __restrict__ Wfc,
                             const float* __restrict__ bfc,
                             float* __restrict__ out) {
    __shared__ float  Wsh[F2 * DOUT];       // 32 KB, layout [k][c]
    __shared__ __half insh[32 * F2];        // 16 KB, 32 rows
    int tid = threadIdx.x;                  // 256
    for (int q = tid; q < F2 * DOUT; q += 256) Wsh[q] = Wfc[q];
    int c  = tid & 31;
    int r4 = tid >> 5;                      // 0..7 -> rows r4*4..r4*4+3
    float bv = bfc[c];
    int rowBase = blockIdx.x * 128;
    for (int g = 0; g < 128; g += 32) {
        __syncthreads();
        // load 32 rows x 128 half2 = 4096 half2 / 256 threads = 16 each
        for (int q = tid; q < 32 * 128; q += 256) {
            int rr = q >> 7, kk2 = q & 127;
            int row = rowBase + g + rr;
            ((__half2*)insh)[q] = (row < NN)
                ? ((const __half2*)(g_out2h + (size_t)row * F2))[kk2]
                : __floats2half2_rn(0.f, 0.f);
        }
        __syncthreads();
        float acc0 = 0.f, acc1 = 0.f, acc2 = 0.f, acc3 = 0.f;
        const uint2* in0 = (const uint2*)(insh + (r4 * 4 + 0) * F2);
        const uint2* in1 = (const uint2*)(insh + (r4 * 4 + 1) * F2);
        const uint2* in2 = (const uint2*)(insh + (r4 * 4 + 2) * F2);
        const uint2* in3 = (const uint2*)(insh + (r4 * 4 + 3) * F2);
#pragma unroll 8
        for (int k4 = 0; k4 < 64; ++k4) {
            uint2 u0 = in0[k4], u1 = in1[k4], u2 = in2[k4], u3 = in3[k4];
            float w0 = Wsh[(4 * k4 + 0) * DOUT + c];
            float w1 = Wsh[(4 * k4 + 1) * DOUT + c];
            float w2 = Wsh[(4 * k4 + 2) * DOUT + c];
            float w3 = Wsh[(4 * k4 + 3) * DOUT + c];
            float2 a0 = __half22float2(*(const __half2*)&u0.x);
            float2 b0 = __half22float2(*(const __half2*)&u0.y);
            float2 a1 = __half22float2(*(const __half2*)&u1.x);
            float2 b1 = __half22float2(*(const __half2*)&u1.y);
            float2 a2 = __half22float2(*(const __half2*)&u2.x);
            float2 b2 = __half22float2(*(const __half2*)&u2.y);
            float2 a3 = __half22float2(*(const __half2*)&u3.x);
            float2 b3 = __half22float2(*(const __half2*)&u3.y);
            acc0 += a0.x * w0 + a0.y * w1 + b0.x * w2 + b0.y * w3;
            acc1 += a1.x * w0 + a1.y * w1 + b1.x * w2 + b1.y * w3;
            acc2 += a2.x * w0 + a2.y * w1 + b2.x * w2 + b2.y * w3;
            acc3 += a3.x * w0 + a3.y * w1 + b3.x * w2 + b3.y * w3;
        }
        int row = rowBase + g + r4 * 4;
        if (row     < NN) out[(row    ) * DOUT + c] = acc0 + bv;
        if (row + 1 < NN) out[(row + 1) * DOUT + c] = acc1 + bv;
        if (row + 2 < NN) out[(row + 2) * DOUT + c] = acc2 + bv;
        if (row + 3 < NN) out[(row + 3) * DOUT + c] = acc3 + bv;
    }
}

// ---------------- launch ----------------------------------------------------
extern "C" void kernel_launch(void* const* d_in, const int* in_sizes, int n_in,
                              void* d_out, int out_size) {
    const float* x       = (const float*)d_in[0];
    const int*   ei      = (const int*)  d_in[1];   // int32 (JAX x64 off)
    const float* W_gcn   = (const float*)d_in[2];
    const float* b_gcn   = (const float*)d_in[3];
    const float* W_gat   = (const float*)d_in[4];
    const float* att_src = (const float*)d_in[5];
    const float* att_dst = (const float*)d_in[6];
    const float* b_gat   = (const float*)d_in[7];
    const float* W_fc    = (const float*)d_in[8];
    const float* b_fc    = (const float*)d_in[9];
    float*       out     = (float*)d_out;

    init_kernel        <<<(NN + 255) / 256, 256>>>();
    deg_kernel         <<<(EE + 255) / 256, 256>>>(ei);
    scan_partial_kernel<<<NB, 256>>>();
    rowptr_kernel      <<<NB, 256>>>();
    csr_fill_kernel    <<<(ET + 255) / 256, 256>>>(ei);

    gemm1_kernel       <<<(NN * 32 + 255) / 256, 256>>>(x, W_gcn);
    gcn_agg_kernel     <<<(NN * 32 + 255) / 256, 256>>>(b_gcn);

    gemm2_kernel       <<<dim3((NN + 63) / 64, 2), 128>>>(W_gat, att_src, att_dst);
    gat_agg_kernel     <<<(NN * 32 + 255) / 256, 256>>>(b_gat);

    gemm3_kernel       <<<(NN + 127) / 128, 256>>>(W_fc, b_fc, out);
}